// round 12
// baseline (speedup 1.0000x reference)
#include <cuda_runtime.h>
#include <cuda_fp16.h>
#include <cuda_bf16.h>
#include <math.h>
#include <stdint.h>

#define N_SRC 100000
#define N_DST 50000
#define D_IN  128
#define D_OUT 64
#define BUCKET 128

#define TILES_Y 1563           // ceil(100000/64)
#define TILES_Z 782            // ceil(50000/64)
#define ASTR 136

// ---------------- scratch (device globals; no allocations allowed) ---------
__device__ __half g_yh[(size_t)N_SRC * D_OUT];     // fp16(x @ W_l)   12.8 MB
__device__ float  g_z[(size_t)N_DST * D_OUT];      // x[:N_DST]@W_r   12.8 MB
__device__ int    g_cnt[N_DST];
__device__ int    g_src[(size_t)N_DST * BUCKET];   // bucketed CSR    25.6 MB
// Pre-swizzled B fragments (exact ldmatrix register images), per type:
// index [(k*4+p)*32 + lane] -> uint4
__device__ uint4 g_bf1[2][1024];                   // W hi part, 32 KB
__device__ uint4 g_bf2[2][1024];                   // W lo part, 32 KB

__device__ __forceinline__ uint32_t smem_u32(const void* p) {
    uint32_t a;
    asm("{ .reg .u64 t; cvta.to.shared.u64 t, %1; cvt.u32.u64 %0, t; }"
        : "=r"(a) : "l"(p));
    return a;
}

// ---------------------------------------------------------------------------
// prep: per-type (blockIdx.x: 0=W_l, 1=W_r) build bf16 hi/lo W^T tiles in
// smem, then warp 0 runs the gemm's exact b-ldmatrix pattern and stores the
// fragment registers to global.
__global__ __launch_bounds__(256) void prep_kernel(const float* __restrict__ Wl,
                                                   const float* __restrict__ Wr) {
    extern __shared__ __align__(16) char psm[];
    __nv_bfloat16* B1 = (__nv_bfloat16*)psm;          // 64 x 136
    __nv_bfloat16* B2 = B1 + 64 * ASTR;
    int type = blockIdx.x;
    const float* W = type ? Wr : Wl;
    int tid = threadIdx.x;

    for (int i = tid; i < 64 * 128; i += 256) {
        int n = i >> 7, k = i & 127;
        float v = W[k * 64 + n];                       // W^T[n][k]
        __nv_bfloat16 h = __float2bfloat16(v);
        B1[n * ASTR + k] = h;
        B2[n * ASTR + k] = __float2bfloat16(v - __bfloat162float(h));
    }
    __syncthreads();

    if (tid < 32) {
        int lane = tid;
        uint32_t b1b = smem_u32(B1), b2b = smem_u32(B2);
        uint32_t boff = (((((lane >> 4) << 3) + (lane & 7)) * ASTR +
                         (((lane >> 3) & 1) << 3)) << 1);
        #pragma unroll
        for (int k = 0; k < 8; k++) {
            #pragma unroll
            for (int p = 0; p < 4; p++) {
                uint32_t po = ((p * ASTR) << 5) + (k << 5);
                uint32_t u0, u1, u2, u3, w0, w1, w2, w3;
                asm volatile("ldmatrix.sync.aligned.m8n8.x4.shared.b16 {%0,%1,%2,%3}, [%4];"
                             : "=r"(u0), "=r"(u1), "=r"(u2), "=r"(u3)
                             : "r"(b1b + boff + po));
                asm volatile("ldmatrix.sync.aligned.m8n8.x4.shared.b16 {%0,%1,%2,%3}, [%4];"
                             : "=r"(w0), "=r"(w1), "=r"(w2), "=r"(w3)
                             : "r"(b2b + boff + po));
                int fi = ((k << 2) + p) * 32 + lane;
                g_bf1[type][fi] = make_uint4(u0, u1, u2, u3);
                g_bf2[type][fi] = make_uint4(w0, w1, w2, w3);
            }
        }
    }
}
#define SM_PREP (2 * 64 * ASTR * 2)

// ---------------------------------------------------------------------------
__global__ void zero_cnt_kernel() {
    int i = blockIdx.x * blockDim.x + threadIdx.x;
    if (i < N_DST) g_cnt[i] = 0;
}

__global__ void fill_kernel(const void* __restrict__ eiv, int n_edges) {
    const unsigned long long* q = (const unsigned long long*)eiv;
    bool is64 = (((q[0] | q[1] | q[2] | q[3]) >> 32) == 0ULL);

    int stride = gridDim.x * blockDim.x;
    for (int e = blockIdx.x * blockDim.x + threadIdx.x; e < n_edges; e += stride) {
        int s, d;
        if (is64) {
            const long long* ei = (const long long*)eiv;
            s = (int)ei[e];
            d = (int)ei[n_edges + e];
        } else {
            const int* ei = (const int*)eiv;
            s = ei[e];
            d = ei[n_edges + e];
        }
        int slot = atomicAdd(&g_cnt[d], 1);
        if (slot < BUCKET)
            g_src[(size_t)d * BUCKET + slot] = s;
    }
}

// ---------------------------------------------------------------------------
// HMMA GEMM: 64x64 tile per CTA, 4 warps, 4 CTAs/SM (A-only smem, capped regs).
// D = A1@W1 + A1@W2 + A2@W1; B fragments come pre-swizzled from global.
__global__ __launch_bounds__(128, 4) void gemm_mma_kernel(const float* __restrict__ x) {
    extern __shared__ __align__(16) char smem_raw[];
    __nv_bfloat16* A1 = (__nv_bfloat16*)smem_raw;            // 64 x 136
    __nv_bfloat16* A2 = A1 + 64 * ASTR;

    int tid = threadIdx.x, warp = tid >> 5, lane = tid & 31;

    int b = blockIdx.x;
    bool is_y;
    int row0, M;
    if (b < TILES_Y) { row0 = b << 6;             M = N_SRC; is_y = true;  }
    else             { row0 = (b - TILES_Y) << 6; M = N_DST; is_y = false; }
    const uint4* bf1 = g_bf1[is_y ? 0 : 1];
    const uint4* bf2 = g_bf2[is_y ? 0 : 1];

    // Load x tile (64x128 fp32), split to bf16 hi/lo
    #pragma unroll
    for (int i = tid; i < 64 * 32; i += 128) {
        int row = i >> 5, c4 = (i & 31) << 2;
        float4 v = make_float4(0.f, 0.f, 0.f, 0.f);
        if (row0 + row < M)
            v = *(const float4*)(x + (size_t)(row0 + row) * D_IN + c4);
        __nv_bfloat16 h0 = __float2bfloat16(v.x), h1 = __float2bfloat16(v.y);
        __nv_bfloat16 h2 = __float2bfloat16(v.z), h3 = __float2bfloat16(v.w);
        __nv_bfloat16 r0 = __float2bfloat16(v.x - __bfloat162float(h0));
        __nv_bfloat16 r1 = __float2bfloat16(v.y - __bfloat162float(h1));
        __nv_bfloat16 r2 = __float2bfloat16(v.z - __bfloat162float(h2));
        __nv_bfloat16 r3 = __float2bfloat16(v.w - __bfloat162float(h3));
        int idx = row * ASTR + c4;
        uint2 hi, lo;
        hi.x = (uint32_t)__bfloat16_as_ushort(h0) | ((uint32_t)__bfloat16_as_ushort(h1) << 16);
        hi.y = (uint32_t)__bfloat16_as_ushort(h2) | ((uint32_t)__bfloat16_as_ushort(h3) << 16);
        lo.x = (uint32_t)__bfloat16_as_ushort(r0) | ((uint32_t)__bfloat16_as_ushort(r1) << 16);
        lo.y = (uint32_t)__bfloat16_as_ushort(r2) | ((uint32_t)__bfloat16_as_ushort(r3) << 16);
        *(uint2*)(A1 + idx) = hi;
        *(uint2*)(A2 + idx) = lo;
    }
    __syncthreads();

    int m0 = warp << 4;
    float c[8][4];
    #pragma unroll
    for (int n = 0; n < 8; n++)
        #pragma unroll
        for (int j = 0; j < 4; j++) c[n][j] = 0.f;

    uint32_t a1b = smem_u32(A1), a2b = smem_u32(A2);
    uint32_t aoff = (((m0 + (lane & 15)) * ASTR + ((lane >> 4) << 3)) << 1);

    #pragma unroll 2
    for (int k = 0; k < 8; k++) {
        uint32_t ka = (k << 5);
        uint32_t x0, x1, x2, x3, y0, y1, y2, y3;
        asm volatile("ldmatrix.sync.aligned.m8n8.x4.shared.b16 {%0,%1,%2,%3}, [%4];"
                     : "=r"(x0), "=r"(x1), "=r"(x2), "=r"(x3)
                     : "r"(a1b + aoff + ka));
        asm volatile("ldmatrix.sync.aligned.m8n8.x4.shared.b16 {%0,%1,%2,%3}, [%4];"
                     : "=r"(y0), "=r"(y1), "=r"(y2), "=r"(y3)
                     : "r"(a2b + aoff + ka));
        #pragma unroll
        for (int p = 0; p < 4; p++) {
            int fi = ((k << 2) + p) * 32 + lane;
            uint4 U = bf1[fi];
            uint4 W4 = bf2[fi];
            int n = p << 1;
            #define MMA(CN, AA0, AA1, AA2, AA3, B0, B1v)                        \
                asm volatile(                                                   \
                    "mma.sync.aligned.m16n8k16.row.col.f32.bf16.bf16.f32 "      \
                    "{%0,%1,%2,%3}, {%4,%5,%6,%7}, {%8,%9}, {%0,%1,%2,%3};"     \
                    : "+f"(c[CN][0]), "+f"(c[CN][1]), "+f"(c[CN][2]), "+f"(c[CN][3]) \
                    : "r"(AA0), "r"(AA1), "r"(AA2), "r"(AA3), "r"(B0), "r"(B1v))
            MMA(n,     x0, x1, x2, x3, U.x, U.y);    // A1*B1
            MMA(n + 1, x0, x1, x2, x3, U.z, U.w);
            MMA(n,     x0, x1, x2, x3, W4.x, W4.y);  // A1*B2
            MMA(n + 1, x0, x1, x2, x3, W4.z, W4.w);
            MMA(n,     y0, y1, y2, y3, U.x, U.y);    // A2*B1
            MMA(n + 1, y0, y1, y2, y3, U.z, U.w);
            #undef MMA
        }
    }

    // Epilogue: c fragment (row gr=lane/4 [+8], cols n*8 + 2*(lane%4) +{0,1})
    int gr = lane >> 2, gc = (lane & 3) << 1;
    int r0 = row0 + m0 + gr;
    int r1 = r0 + 8;
    if (is_y) {
        #pragma unroll
        for (int n = 0; n < 8; n++) {
            int col = (n << 3) + gc;
            if (r0 < M)
                *(__half2*)(g_yh + (size_t)r0 * D_OUT + col) =
                    __floats2half2_rn(c[n][0], c[n][1]);
            if (r1 < M)
                *(__half2*)(g_yh + (size_t)r1 * D_OUT + col) =
                    __floats2half2_rn(c[n][2], c[n][3]);
        }
    } else {
        #pragma unroll
        for (int n = 0; n < 8; n++) {
            int col = (n << 3) + gc;
            if (r0 < M)
                *(float2*)(g_z + (size_t)r0 * D_OUT + col) = make_float2(c[n][0], c[n][1]);
            if (r1 < M)
                *(float2*)(g_z + (size_t)r1 * D_OUT + col) = make_float2(c[n][2], c[n][3]);
        }
    }
}
#define SM_GEMM (2 * 64 * ASTR * 2)

// ---------------------------------------------------------------------------
// Gather + finalize (R7 version — measured 35.1us): one warp per dst row;
// lane owns cols {2l, 2l+1}. 8 predicated independent gathers in flight per
// lane (MLP=8) with int4 index prefetch; scalar float accumulation.
__global__ __launch_bounds__(256) void gather_finalize_kernel(
        float* __restrict__ out, const float* __restrict__ b_l) {
    int warp = (blockIdx.x * blockDim.x + threadIdx.x) >> 5;
    int lane = threadIdx.x & 31;
    if (warp >= N_DST) return;

    int cnt = g_cnt[warp];
    int n = cnt < BUCKET ? cnt : BUCKET;
    const int* bucket = g_src + (size_t)warp * BUCKET;
    const __half2* yh = (const __half2*)g_yh + lane;   // row r -> yh[r*32]

    float a0 = 0.f, a1 = 0.f;
    if (n > 0) {
        __half2 zero = __half2half2(__ushort_as_half(0));
        int4 p0 = *(const int4*)bucket;
        int4 p1 = *(const int4*)(bucket + 4);
        for (int g = 0; g < n; g += 8) {
            int4 c0 = p0, c1 = p1;
            if (g + 8 < n) {
                p0 = *(const int4*)(bucket + g + 8);
                p1 = *(const int4*)(bucket + g + 12);
            }
            __half2 h0 = (g + 0 < n) ? yh[(size_t)c0.x << 5] : zero;
            __half2 h1 = (g + 1 < n) ? yh[(size_t)c0.y << 5] : zero;
            __half2 h2 = (g + 2 < n) ? yh[(size_t)c0.z << 5] : zero;
            __half2 h3 = (g + 3 < n) ? yh[(size_t)c0.w << 5] : zero;
            __half2 h4 = (g + 4 < n) ? yh[(size_t)c1.x << 5] : zero;
            __half2 h5 = (g + 5 < n) ? yh[(size_t)c1.y << 5] : zero;
            __half2 h6 = (g + 6 < n) ? yh[(size_t)c1.z << 5] : zero;
            __half2 h7 = (g + 7 < n) ? yh[(size_t)c1.w << 5] : zero;
            float2 f0 = __half22float2(h0), f1 = __half22float2(h1);
            float2 f2 = __half22float2(h2), f3 = __half22float2(h3);
            float2 f4 = __half22float2(h4), f5 = __half22float2(h5);
            float2 f6 = __half22float2(h6), f7 = __half22float2(h7);
            a0 += (f0.x + f1.x) + (f2.x + f3.x) + (f4.x + f5.x) + (f6.x + f7.x);
            a1 += (f0.y + f1.y) + (f2.y + f3.y) + (f4.y + f5.y) + (f6.y + f7.y);
        }
    }

    float inv = 1.0f / fmaxf((float)cnt, 1.0f);
    float2 zz = *(const float2*)(g_z + (size_t)warp * D_OUT + (lane << 1));
    float2 bb = *(const float2*)(b_l + (lane << 1));
    float v0 = a0 * inv + bb.x + zz.x;
    float v1 = a1 * inv + bb.y + zz.y;

    float m = fmaxf(v0, v1);
    #pragma unroll
    for (int o = 16; o; o >>= 1) m = fmaxf(m, __shfl_xor_sync(0xffffffffu, m, o));

    float s = __expf(v0 - m) + __expf(v1 - m);
    #pragma unroll
    for (int o = 16; o; o >>= 1) s += __shfl_xor_sync(0xffffffffu, s, o);

    float lz = m + __logf(s);
    *(float2*)(out + (size_t)warp * D_OUT + (lane << 1)) =
        make_float2(v0 - lz, v1 - lz);
}

// ---------------------------------------------------------------------------
extern "C" void kernel_launch(void* const* d_in, const int* in_sizes, int n_in,
                              void* d_out, int out_size) {
    const float* x  = (const float*)d_in[0];
    const float* Wl = (const float*)d_in[1];
    const float* bl = (const float*)d_in[2];
    const float* Wr = (const float*)d_in[3];
    const void*  ei = d_in[4];
    int n_edges = in_sizes[4] / 2;
    float* out = (float*)d_out;

    static bool attr_done = false;
    if (!attr_done) {
        attr_done = true;
        cudaFuncSetAttribute(prep_kernel,
                             cudaFuncAttributeMaxDynamicSharedMemorySize, SM_PREP);
        cudaFuncSetAttribute(gemm_mma_kernel,
                             cudaFuncAttributeMaxDynamicSharedMemorySize, SM_GEMM);
    }

    zero_cnt_kernel<<<(N_DST + 255) / 256, 256>>>();
    fill_kernel<<<2048, 256>>>(ei, n_edges);
    prep_kernel<<<2, 256, SM_PREP>>>(Wl, Wr);
    gemm_mma_kernel<<<TILES_Y + TILES_Z, 128, SM_GEMM>>>(x);
    gather_finalize_kernel<<<(N_DST * 32 + 255) / 256, 256>>>(out, bl);
}

// round 13
// speedup vs baseline: 1.0540x; 1.0540x over previous
#include <cuda_runtime.h>
#include <cuda_fp16.h>
#include <cuda_bf16.h>
#include <math.h>
#include <stdint.h>

#define N_SRC 100000
#define N_DST 50000
#define D_IN  128
#define D_OUT 64
#define BUCKET 128

#define TILES_Y 1563           // ceil(100000/64)
#define TILES_Z 782            // ceil(50000/64)
#define ASTR 136

// ---------------- scratch (device globals; no allocations allowed) ---------
__device__ __half g_yh[(size_t)N_SRC * D_OUT];     // fp16(x @ W_l)   12.8 MB
__device__ float  g_z[(size_t)N_DST * D_OUT];      // x[:N_DST]@W_r   12.8 MB
__device__ int    g_cnt[N_DST];                    // zero-init at load; gather
                                                   // re-zeroes after each use
__device__ int    g_src[(size_t)N_DST * BUCKET];   // bucketed CSR    25.6 MB
// Pre-swizzled B fragments (exact ldmatrix register images), per type:
__device__ uint4 g_bf1[2][1024];                   // W hi part, 32 KB
__device__ uint4 g_bf2[2][1024];                   // W lo part, 32 KB

__device__ __forceinline__ uint32_t smem_u32(const void* p) {
    uint32_t a;
    asm("{ .reg .u64 t; cvta.to.shared.u64 t, %1; cvt.u32.u64 %0, t; }"
        : "=r"(a) : "l"(p));
    return a;
}

// ---------------------------------------------------------------------------
// prep: per-type (blockIdx.x: 0=W_l, 1=W_r) build bf16 hi/lo W^T tiles in
// smem, then warp 0 runs the gemm's exact b-ldmatrix pattern and stores the
// fragment registers to global. Never touches g_cnt/g_src.
__global__ __launch_bounds__(256) void prep_kernel(const float* __restrict__ Wl,
                                                   const float* __restrict__ Wr) {
    extern __shared__ __align__(16) char psm[];
    __nv_bfloat16* B1 = (__nv_bfloat16*)psm;          // 64 x 136
    __nv_bfloat16* B2 = B1 + 64 * ASTR;
    int type = blockIdx.x;
    const float* W = type ? Wr : Wl;
    int tid = threadIdx.x;

    for (int i = tid; i < 64 * 128; i += 256) {
        int n = i >> 7, k = i & 127;
        float v = W[k * 64 + n];                       // W^T[n][k]
        __nv_bfloat16 h = __float2bfloat16(v);
        B1[n * ASTR + k] = h;
        B2[n * ASTR + k] = __float2bfloat16(v - __bfloat162float(h));
    }
    __syncthreads();

    if (tid < 32) {
        int lane = tid;
        uint32_t b1b = smem_u32(B1), b2b = smem_u32(B2);
        uint32_t boff = (((((lane >> 4) << 3) + (lane & 7)) * ASTR +
                         (((lane >> 3) & 1) << 3)) << 1);
        #pragma unroll
        for (int k = 0; k < 8; k++) {
            #pragma unroll
            for (int p = 0; p < 4; p++) {
                uint32_t po = ((p * ASTR) << 5) + (k << 5);
                uint32_t u0, u1, u2, u3, w0, w1, w2, w3;
                asm volatile("ldmatrix.sync.aligned.m8n8.x4.shared.b16 {%0,%1,%2,%3}, [%4];"
                             : "=r"(u0), "=r"(u1), "=r"(u2), "=r"(u3)
                             : "r"(b1b + boff + po));
                asm volatile("ldmatrix.sync.aligned.m8n8.x4.shared.b16 {%0,%1,%2,%3}, [%4];"
                             : "=r"(w0), "=r"(w1), "=r"(w2), "=r"(w3)
                             : "r"(b2b + boff + po));
                int fi = ((k << 2) + p) * 32 + lane;
                g_bf1[type][fi] = make_uint4(u0, u1, u2, u3);
                g_bf2[type][fi] = make_uint4(w0, w1, w2, w3);
            }
        }
    }
}
#define SM_PREP (2 * 64 * ASTR * 2)

// ---------------------------------------------------------------------------
// fill: counters start at 0 (zero-init on first run; re-zeroed by gather on
// every subsequent graph replay).
__global__ void fill_kernel(const void* __restrict__ eiv, int n_edges) {
    const unsigned long long* q = (const unsigned long long*)eiv;
    bool is64 = (((q[0] | q[1] | q[2] | q[3]) >> 32) == 0ULL);

    int stride = gridDim.x * blockDim.x;
    for (int e = blockIdx.x * blockDim.x + threadIdx.x; e < n_edges; e += stride) {
        int s, d;
        if (is64) {
            const long long* ei = (const long long*)eiv;
            s = (int)ei[e];
            d = (int)ei[n_edges + e];
        } else {
            const int* ei = (const int*)eiv;
            s = ei[e];
            d = ei[n_edges + e];
        }
        int slot = atomicAdd(&g_cnt[d], 1);
        if (slot < BUCKET)
            g_src[(size_t)d * BUCKET + slot] = s;
    }
}

// ---------------------------------------------------------------------------
// HMMA GEMM: 64x64 tile per CTA, 4 warps, 4 CTAs/SM (A-only smem, capped regs).
// D = A1@W1 + A1@W2 + A2@W1; B fragments come pre-swizzled from global.
__global__ __launch_bounds__(128, 4) void gemm_mma_kernel(const float* __restrict__ x) {
    extern __shared__ __align__(16) char smem_raw[];
    __nv_bfloat16* A1 = (__nv_bfloat16*)smem_raw;            // 64 x 136
    __nv_bfloat16* A2 = A1 + 64 * ASTR;

    int tid = threadIdx.x, warp = tid >> 5, lane = tid & 31;

    int b = blockIdx.x;
    bool is_y;
    int row0, M;
    if (b < TILES_Y) { row0 = b << 6;             M = N_SRC; is_y = true;  }
    else             { row0 = (b - TILES_Y) << 6; M = N_DST; is_y = false; }
    const uint4* bf1 = g_bf1[is_y ? 0 : 1];
    const uint4* bf2 = g_bf2[is_y ? 0 : 1];

    // Load x tile (64x128 fp32), split to bf16 hi/lo
    #pragma unroll
    for (int i = tid; i < 64 * 32; i += 128) {
        int row = i >> 5, c4 = (i & 31) << 2;
        float4 v = make_float4(0.f, 0.f, 0.f, 0.f);
        if (row0 + row < M)
            v = *(const float4*)(x + (size_t)(row0 + row) * D_IN + c4);
        __nv_bfloat16 h0 = __float2bfloat16(v.x), h1 = __float2bfloat16(v.y);
        __nv_bfloat16 h2 = __float2bfloat16(v.z), h3 = __float2bfloat16(v.w);
        __nv_bfloat16 r0 = __float2bfloat16(v.x - __bfloat162float(h0));
        __nv_bfloat16 r1 = __float2bfloat16(v.y - __bfloat162float(h1));
        __nv_bfloat16 r2 = __float2bfloat16(v.z - __bfloat162float(h2));
        __nv_bfloat16 r3 = __float2bfloat16(v.w - __bfloat162float(h3));
        int idx = row * ASTR + c4;
        uint2 hi, lo;
        hi.x = (uint32_t)__bfloat16_as_ushort(h0) | ((uint32_t)__bfloat16_as_ushort(h1) << 16);
        hi.y = (uint32_t)__bfloat16_as_ushort(h2) | ((uint32_t)__bfloat16_as_ushort(h3) << 16);
        lo.x = (uint32_t)__bfloat16_as_ushort(r0) | ((uint32_t)__bfloat16_as_ushort(r1) << 16);
        lo.y = (uint32_t)__bfloat16_as_ushort(r2) | ((uint32_t)__bfloat16_as_ushort(r3) << 16);
        *(uint2*)(A1 + idx) = hi;
        *(uint2*)(A2 + idx) = lo;
    }
    __syncthreads();

    int m0 = warp << 4;
    float c[8][4];
    #pragma unroll
    for (int n = 0; n < 8; n++)
        #pragma unroll
        for (int j = 0; j < 4; j++) c[n][j] = 0.f;

    uint32_t a1b = smem_u32(A1), a2b = smem_u32(A2);
    uint32_t aoff = (((m0 + (lane & 15)) * ASTR + ((lane >> 4) << 3)) << 1);

    #pragma unroll 2
    for (int k = 0; k < 8; k++) {
        uint32_t ka = (k << 5);
        uint32_t x0, x1, x2, x3, y0, y1, y2, y3;
        asm volatile("ldmatrix.sync.aligned.m8n8.x4.shared.b16 {%0,%1,%2,%3}, [%4];"
                     : "=r"(x0), "=r"(x1), "=r"(x2), "=r"(x3)
                     : "r"(a1b + aoff + ka));
        asm volatile("ldmatrix.sync.aligned.m8n8.x4.shared.b16 {%0,%1,%2,%3}, [%4];"
                     : "=r"(y0), "=r"(y1), "=r"(y2), "=r"(y3)
                     : "r"(a2b + aoff + ka));
        #pragma unroll
        for (int p = 0; p < 4; p++) {
            int fi = ((k << 2) + p) * 32 + lane;
            uint4 U = bf1[fi];
            uint4 W4 = bf2[fi];
            int n = p << 1;
            #define MMA(CN, AA0, AA1, AA2, AA3, B0, B1v)                        \
                asm volatile(                                                   \
                    "mma.sync.aligned.m16n8k16.row.col.f32.bf16.bf16.f32 "      \
                    "{%0,%1,%2,%3}, {%4,%5,%6,%7}, {%8,%9}, {%0,%1,%2,%3};"     \
                    : "+f"(c[CN][0]), "+f"(c[CN][1]), "+f"(c[CN][2]), "+f"(c[CN][3]) \
                    : "r"(AA0), "r"(AA1), "r"(AA2), "r"(AA3), "r"(B0), "r"(B1v))
            MMA(n,     x0, x1, x2, x3, U.x, U.y);    // A1*B1
            MMA(n + 1, x0, x1, x2, x3, U.z, U.w);
            MMA(n,     x0, x1, x2, x3, W4.x, W4.y);  // A1*B2
            MMA(n + 1, x0, x1, x2, x3, W4.z, W4.w);
            MMA(n,     y0, y1, y2, y3, U.x, U.y);    // A2*B1
            MMA(n + 1, y0, y1, y2, y3, U.z, U.w);
            #undef MMA
        }
    }

    // Epilogue: c fragment (row gr=lane/4 [+8], cols n*8 + 2*(lane%4) +{0,1})
    int gr = lane >> 2, gc = (lane & 3) << 1;
    int r0 = row0 + m0 + gr;
    int r1 = r0 + 8;
    if (is_y) {
        #pragma unroll
        for (int n = 0; n < 8; n++) {
            int col = (n << 3) + gc;
            if (r0 < M)
                *(__half2*)(g_yh + (size_t)r0 * D_OUT + col) =
                    __floats2half2_rn(c[n][0], c[n][1]);
            if (r1 < M)
                *(__half2*)(g_yh + (size_t)r1 * D_OUT + col) =
                    __floats2half2_rn(c[n][2], c[n][3]);
        }
    } else {
        #pragma unroll
        for (int n = 0; n < 8; n++) {
            int col = (n << 3) + gc;
            if (r0 < M)
                *(float2*)(g_z + (size_t)r0 * D_OUT + col) = make_float2(c[n][0], c[n][1]);
            if (r1 < M)
                *(float2*)(g_z + (size_t)r1 * D_OUT + col) = make_float2(c[n][2], c[n][3]);
        }
    }
}
#define SM_GEMM (2 * 64 * ASTR * 2)

// ---------------------------------------------------------------------------
// Gather + finalize: one warp per dst row; lane owns cols {2l, 2l+1} (half2).
// R7 memory pattern (8 predicated 4B gathers in flight, int4 index prefetch)
// + fp16 depth-3 __hadd2 reduction tree + packed f32x2 accumulate.
// Re-zeroes g_cnt[warp] at the end (replaces the zero_cnt kernel).
__global__ __launch_bounds__(256) void gather_finalize_kernel(
        float* __restrict__ out, const float* __restrict__ b_l) {
    int warp = (blockIdx.x * blockDim.x + threadIdx.x) >> 5;
    int lane = threadIdx.x & 31;
    if (warp >= N_DST) return;

    int cnt = g_cnt[warp];
    int n = cnt < BUCKET ? cnt : BUCKET;
    const int* bucket = g_src + (size_t)warp * BUCKET;
    const __half2* yh = (const __half2*)g_yh + lane;   // row r -> yh[r*32]

    unsigned long long acc = 0ULL;                     // packed float2
    if (n > 0) {
        __half2 zero = __half2half2(__ushort_as_half(0));
        int4 p0 = *(const int4*)bucket;
        int4 p1 = *(const int4*)(bucket + 4);
        for (int g = 0; g < n; g += 8) {
            int4 c0 = p0, c1 = p1;
            if (g + 8 < n) {
                p0 = *(const int4*)(bucket + g + 8);
                p1 = *(const int4*)(bucket + g + 12);
            }
            __half2 h0 = (g + 0 < n) ? yh[(size_t)c0.x << 5] : zero;
            __half2 h1 = (g + 1 < n) ? yh[(size_t)c0.y << 5] : zero;
            __half2 h2 = (g + 2 < n) ? yh[(size_t)c0.z << 5] : zero;
            __half2 h3 = (g + 3 < n) ? yh[(size_t)c0.w << 5] : zero;
            __half2 h4 = (g + 4 < n) ? yh[(size_t)c1.x << 5] : zero;
            __half2 h5 = (g + 5 < n) ? yh[(size_t)c1.y << 5] : zero;
            __half2 h6 = (g + 6 < n) ? yh[(size_t)c1.z << 5] : zero;
            __half2 h7 = (g + 7 < n) ? yh[(size_t)c1.w << 5] : zero;
            __half2 t = __hadd2(__hadd2(__hadd2(h0, h1), __hadd2(h2, h3)),
                                __hadd2(__hadd2(h4, h5), __hadd2(h6, h7)));
            float2 f = __half22float2(t);
            unsigned long long fp;
            asm("mov.b64 %0, {%1, %2};" : "=l"(fp) : "f"(f.x), "f"(f.y));
            asm("add.rn.f32x2 %0, %0, %1;" : "+l"(acc) : "l"(fp));
        }
    }

    float a0, a1;
    asm("mov.b64 {%0, %1}, %2;" : "=f"(a0), "=f"(a1) : "l"(acc));

    float inv = 1.0f / fmaxf((float)cnt, 1.0f);
    float2 zz = *(const float2*)(g_z + (size_t)warp * D_OUT + (lane << 1));
    float2 bb = *(const float2*)(b_l + (lane << 1));
    float v0 = a0 * inv + bb.x + zz.x;
    float v1 = a1 * inv + bb.y + zz.y;

    float m = fmaxf(v0, v1);
    #pragma unroll
    for (int o = 16; o; o >>= 1) m = fmaxf(m, __shfl_xor_sync(0xffffffffu, m, o));

    float s = __expf(v0 - m) + __expf(v1 - m);
    #pragma unroll
    for (int o = 16; o; o >>= 1) s += __shfl_xor_sync(0xffffffffu, s, o);

    float lz = m + __logf(s);
    *(float2*)(out + (size_t)warp * D_OUT + (lane << 1)) =
        make_float2(v0 - lz, v1 - lz);

    // reset the counter for the next graph replay (fill assumes zeros)
    if (lane == 0) g_cnt[warp] = 0;
}

// ---------------------------------------------------------------------------
extern "C" void kernel_launch(void* const* d_in, const int* in_sizes, int n_in,
                              void* d_out, int out_size) {
    const float* x  = (const float*)d_in[0];
    const float* Wl = (const float*)d_in[1];
    const float* bl = (const float*)d_in[2];
    const float* Wr = (const float*)d_in[3];
    const void*  ei = d_in[4];
    int n_edges = in_sizes[4] / 2;
    float* out = (float*)d_out;

    static bool attr_done = false;
    if (!attr_done) {
        attr_done = true;
        cudaFuncSetAttribute(prep_kernel,
                             cudaFuncAttributeMaxDynamicSharedMemorySize, SM_PREP);
        cudaFuncSetAttribute(gemm_mma_kernel,
                             cudaFuncAttributeMaxDynamicSharedMemorySize, SM_GEMM);
    }

    fill_kernel<<<2048, 256>>>(ei, n_edges);
    prep_kernel<<<2, 256, SM_PREP>>>(Wl, Wr);
    gemm_mma_kernel<<<TILES_Y + TILES_Z, 128, SM_GEMM>>>(x);
    gather_finalize_kernel<<<(N_DST * 32 + 255) / 256, 256>>>(out, bl);
}

// round 14
// speedup vs baseline: 1.0937x; 1.0377x over previous
#include <cuda_runtime.h>
#include <cuda_fp16.h>
#include <cuda_bf16.h>
#include <math.h>
#include <stdint.h>

#define N_SRC 100000
#define N_DST 50000
#define D_IN  128
#define D_OUT 64
#define BUCKET 128

#define TILES_Y 1563           // ceil(100000/64)
#define TILES_Z 782            // ceil(50000/64)
#define ASTR 136

// ---------------- scratch (device globals; no allocations allowed) ---------
__device__ __half g_yh[(size_t)N_SRC * D_OUT];     // fp16(x @ W_l)   12.8 MB
__device__ float  g_z[(size_t)N_DST * D_OUT];      // x[:N_DST]@W_r   12.8 MB
__device__ int    g_cnt[N_DST];                    // zero-init; gather re-zeroes
__device__ int    g_src[(size_t)N_DST * BUCKET];   // bucketed CSR    25.6 MB
// Pre-swizzled B fragments (exact ldmatrix register images), per type:
__device__ uint4 g_bf1[2][1024];                   // W hi part, 32 KB
__device__ uint4 g_bf2[2][1024];                   // W lo part, 32 KB

__device__ __forceinline__ uint32_t smem_u32(const void* p) {
    uint32_t a;
    asm("{ .reg .u64 t; cvta.to.shared.u64 t, %1; cvt.u32.u64 %0, t; }"
        : "=r"(a) : "l"(p));
    return a;
}

// ---------------------------------------------------------------------------
// prep: per-type (blockIdx.x: 0=W_l, 1=W_r) build bf16 hi/lo W^T tiles in
// smem, then warp 0 runs the gemm's exact b-ldmatrix pattern and stores the
// fragment registers to global. Never touches g_cnt/g_src.
__global__ __launch_bounds__(256) void prep_kernel(const float* __restrict__ Wl,
                                                   const float* __restrict__ Wr) {
    extern __shared__ __align__(16) char psm[];
    __nv_bfloat16* B1 = (__nv_bfloat16*)psm;          // 64 x 136
    __nv_bfloat16* B2 = B1 + 64 * ASTR;
    int type = blockIdx.x;
    const float* W = type ? Wr : Wl;
    int tid = threadIdx.x;

    for (int i = tid; i < 64 * 128; i += 256) {
        int n = i >> 7, k = i & 127;
        float v = W[k * 64 + n];                       // W^T[n][k]
        __nv_bfloat16 h = __float2bfloat16(v);
        B1[n * ASTR + k] = h;
        B2[n * ASTR + k] = __float2bfloat16(v - __bfloat162float(h));
    }
    __syncthreads();

    if (tid < 32) {
        int lane = tid;
        uint32_t b1b = smem_u32(B1), b2b = smem_u32(B2);
        uint32_t boff = (((((lane >> 4) << 3) + (lane & 7)) * ASTR +
                         (((lane >> 3) & 1) << 3)) << 1);
        #pragma unroll
        for (int k = 0; k < 8; k++) {
            #pragma unroll
            for (int p = 0; p < 4; p++) {
                uint32_t po = ((p * ASTR) << 5) + (k << 5);
                uint32_t u0, u1, u2, u3, w0, w1, w2, w3;
                asm volatile("ldmatrix.sync.aligned.m8n8.x4.shared.b16 {%0,%1,%2,%3}, [%4];"
                             : "=r"(u0), "=r"(u1), "=r"(u2), "=r"(u3)
                             : "r"(b1b + boff + po));
                asm volatile("ldmatrix.sync.aligned.m8n8.x4.shared.b16 {%0,%1,%2,%3}, [%4];"
                             : "=r"(w0), "=r"(w1), "=r"(w2), "=r"(w3)
                             : "r"(b2b + boff + po));
                int fi = ((k << 2) + p) * 32 + lane;
                g_bf1[type][fi] = make_uint4(u0, u1, u2, u3);
                g_bf2[type][fi] = make_uint4(w0, w1, w2, w3);
            }
        }
    }
}
#define SM_PREP (2 * 64 * ASTR * 2)

// ---------------------------------------------------------------------------
__global__ void fill_kernel(const void* __restrict__ eiv, int n_edges) {
    const unsigned long long* q = (const unsigned long long*)eiv;
    bool is64 = (((q[0] | q[1] | q[2] | q[3]) >> 32) == 0ULL);

    int stride = gridDim.x * blockDim.x;
    for (int e = blockIdx.x * blockDim.x + threadIdx.x; e < n_edges; e += stride) {
        int s, d;
        if (is64) {
            const long long* ei = (const long long*)eiv;
            s = (int)ei[e];
            d = (int)ei[n_edges + e];
        } else {
            const int* ei = (const int*)eiv;
            s = ei[e];
            d = ei[n_edges + e];
        }
        int slot = atomicAdd(&g_cnt[d], 1);
        if (slot < BUCKET)
            g_src[(size_t)d * BUCKET + slot] = s;
    }
}

// ---------------------------------------------------------------------------
// HMMA GEMM: 64x64 tile per CTA, 4 warps, 4 CTAs/SM (A-only smem, capped regs).
// D = A1@W1 + A1@W2 + A2@W1; B fragments come pre-swizzled from global.
__global__ __launch_bounds__(128, 4) void gemm_mma_kernel(const float* __restrict__ x) {
    extern __shared__ __align__(16) char smem_raw[];
    __nv_bfloat16* A1 = (__nv_bfloat16*)smem_raw;            // 64 x 136
    __nv_bfloat16* A2 = A1 + 64 * ASTR;

    int tid = threadIdx.x, warp = tid >> 5, lane = tid & 31;

    int b = blockIdx.x;
    bool is_y;
    int row0, M;
    if (b < TILES_Y) { row0 = b << 6;             M = N_SRC; is_y = true;  }
    else             { row0 = (b - TILES_Y) << 6; M = N_DST; is_y = false; }
    const uint4* bf1 = g_bf1[is_y ? 0 : 1];
    const uint4* bf2 = g_bf2[is_y ? 0 : 1];

    // Load x tile (64x128 fp32), split to bf16 hi/lo
    #pragma unroll
    for (int i = tid; i < 64 * 32; i += 128) {
        int row = i >> 5, c4 = (i & 31) << 2;
        float4 v = make_float4(0.f, 0.f, 0.f, 0.f);
        if (row0 + row < M)
            v = *(const float4*)(x + (size_t)(row0 + row) * D_IN + c4);
        __nv_bfloat16 h0 = __float2bfloat16(v.x), h1 = __float2bfloat16(v.y);
        __nv_bfloat16 h2 = __float2bfloat16(v.z), h3 = __float2bfloat16(v.w);
        __nv_bfloat16 r0 = __float2bfloat16(v.x - __bfloat162float(h0));
        __nv_bfloat16 r1 = __float2bfloat16(v.y - __bfloat162float(h1));
        __nv_bfloat16 r2 = __float2bfloat16(v.z - __bfloat162float(h2));
        __nv_bfloat16 r3 = __float2bfloat16(v.w - __bfloat162float(h3));
        int idx = row * ASTR + c4;
        uint2 hi, lo;
        hi.x = (uint32_t)__bfloat16_as_ushort(h0) | ((uint32_t)__bfloat16_as_ushort(h1) << 16);
        hi.y = (uint32_t)__bfloat16_as_ushort(h2) | ((uint32_t)__bfloat16_as_ushort(h3) << 16);
        lo.x = (uint32_t)__bfloat16_as_ushort(r0) | ((uint32_t)__bfloat16_as_ushort(r1) << 16);
        lo.y = (uint32_t)__bfloat16_as_ushort(r2) | ((uint32_t)__bfloat16_as_ushort(r3) << 16);
        *(uint2*)(A1 + idx) = hi;
        *(uint2*)(A2 + idx) = lo;
    }
    __syncthreads();

    int m0 = warp << 4;
    float c[8][4];
    #pragma unroll
    for (int n = 0; n < 8; n++)
        #pragma unroll
        for (int j = 0; j < 4; j++) c[n][j] = 0.f;

    uint32_t a1b = smem_u32(A1), a2b = smem_u32(A2);
    uint32_t aoff = (((m0 + (lane & 15)) * ASTR + ((lane >> 4) << 3)) << 1);

    #pragma unroll 2
    for (int k = 0; k < 8; k++) {
        uint32_t ka = (k << 5);
        uint32_t x0, x1, x2, x3, y0, y1, y2, y3;
        asm volatile("ldmatrix.sync.aligned.m8n8.x4.shared.b16 {%0,%1,%2,%3}, [%4];"
                     : "=r"(x0), "=r"(x1), "=r"(x2), "=r"(x3)
                     : "r"(a1b + aoff + ka));
        asm volatile("ldmatrix.sync.aligned.m8n8.x4.shared.b16 {%0,%1,%2,%3}, [%4];"
                     : "=r"(y0), "=r"(y1), "=r"(y2), "=r"(y3)
                     : "r"(a2b + aoff + ka));
        #pragma unroll
        for (int p = 0; p < 4; p++) {
            int fi = ((k << 2) + p) * 32 + lane;
            uint4 U = bf1[fi];
            uint4 W4 = bf2[fi];
            int n = p << 1;
            #define MMA(CN, AA0, AA1, AA2, AA3, B0, B1v)                        \
                asm volatile(                                                   \
                    "mma.sync.aligned.m16n8k16.row.col.f32.bf16.bf16.f32 "      \
                    "{%0,%1,%2,%3}, {%4,%5,%6,%7}, {%8,%9}, {%0,%1,%2,%3};"     \
                    : "+f"(c[CN][0]), "+f"(c[CN][1]), "+f"(c[CN][2]), "+f"(c[CN][3]) \
                    : "r"(AA0), "r"(AA1), "r"(AA2), "r"(AA3), "r"(B0), "r"(B1v))
            MMA(n,     x0, x1, x2, x3, U.x, U.y);    // A1*B1
            MMA(n + 1, x0, x1, x2, x3, U.z, U.w);
            MMA(n,     x0, x1, x2, x3, W4.x, W4.y);  // A1*B2
            MMA(n + 1, x0, x1, x2, x3, W4.z, W4.w);
            MMA(n,     y0, y1, y2, y3, U.x, U.y);    // A2*B1
            MMA(n + 1, y0, y1, y2, y3, U.z, U.w);
            #undef MMA
        }
    }

    // Epilogue: c fragment (row gr=lane/4 [+8], cols n*8 + 2*(lane%4) +{0,1})
    int gr = lane >> 2, gc = (lane & 3) << 1;
    int r0 = row0 + m0 + gr;
    int r1 = r0 + 8;
    if (is_y) {
        #pragma unroll
        for (int n = 0; n < 8; n++) {
            int col = (n << 3) + gc;
            if (r0 < M)
                *(__half2*)(g_yh + (size_t)r0 * D_OUT + col) =
                    __floats2half2_rn(c[n][0], c[n][1]);
            if (r1 < M)
                *(__half2*)(g_yh + (size_t)r1 * D_OUT + col) =
                    __floats2half2_rn(c[n][2], c[n][3]);
        }
    } else {
        #pragma unroll
        for (int n = 0; n < 8; n++) {
            int col = (n << 3) + gc;
            if (r0 < M)
                *(float2*)(g_z + (size_t)r0 * D_OUT + col) = make_float2(c[n][0], c[n][1]);
            if (r1 < M)
                *(float2*)(g_z + (size_t)r1 * D_OUT + col) = make_float2(c[n][2], c[n][3]);
        }
    }
}
#define SM_GEMM (2 * 64 * ASTR * 2)

// ---------------------------------------------------------------------------
// Gather + finalize: one warp per dst row, 16 lanes per row (uint2 = 8B =
// cols 4l..4l+3), sub-half-warps take alternate edges. 8 predicated
// independent LDG.64 in flight per lane => 16 edges per iteration, MLP=8.
// fp32 scalar accumulation (independent chains), shfl-16 merge, 16-lane
// softmax. Re-zeroes g_cnt[warp] at the end.
__global__ __launch_bounds__(256) void gather_finalize_kernel(
        float* __restrict__ out, const float* __restrict__ b_l) {
    int warp = (blockIdx.x * blockDim.x + threadIdx.x) >> 5;
    int lane = threadIdx.x & 31;
    if (warp >= N_DST) return;

    int cnt = g_cnt[warp];
    int n = cnt < BUCKET ? cnt : BUCKET;
    const int* bucket = g_src + (size_t)warp * BUCKET;
    int sub = lane >> 4, l = lane & 15;
    const uint2* yh2 = (const uint2*)g_yh + l;     // row r -> yh2[r*16]

    float a0 = 0.f, a1 = 0.f, a2 = 0.f, a3 = 0.f;
    uint2 zero2 = make_uint2(0u, 0u);
    for (int g = 0; g < n; g += 16) {
        int4 c0 = *(const int4*)(bucket + g);
        int4 c1 = *(const int4*)(bucket + g + 4);
        int4 c2 = *(const int4*)(bucket + g + 8);
        int4 c3 = *(const int4*)(bucket + g + 12);
        // my 8 edges: g + 2j + sub, j = 0..7
        int s0 = sub ? c0.y : c0.x;
        int s1 = sub ? c0.w : c0.z;
        int s2 = sub ? c1.y : c1.x;
        int s3 = sub ? c1.w : c1.z;
        int s4 = sub ? c2.y : c2.x;
        int s5 = sub ? c2.w : c2.z;
        int s6 = sub ? c3.y : c3.x;
        int s7 = sub ? c3.w : c3.z;
        uint2 u0 = (g + 0  + sub < n) ? yh2[(size_t)s0 << 4] : zero2;
        uint2 u1 = (g + 2  + sub < n) ? yh2[(size_t)s1 << 4] : zero2;
        uint2 u2 = (g + 4  + sub < n) ? yh2[(size_t)s2 << 4] : zero2;
        uint2 u3 = (g + 6  + sub < n) ? yh2[(size_t)s3 << 4] : zero2;
        uint2 u4 = (g + 8  + sub < n) ? yh2[(size_t)s4 << 4] : zero2;
        uint2 u5 = (g + 10 + sub < n) ? yh2[(size_t)s5 << 4] : zero2;
        uint2 u6 = (g + 12 + sub < n) ? yh2[(size_t)s6 << 4] : zero2;
        uint2 u7 = (g + 14 + sub < n) ? yh2[(size_t)s7 << 4] : zero2;
        #define ACCUM(U)                                                        \
            { float2 fl = __half22float2(*(__half2*)&(U).x);                    \
              float2 fh = __half22float2(*(__half2*)&(U).y);                    \
              a0 += fl.x; a1 += fl.y; a2 += fh.x; a3 += fh.y; }
        ACCUM(u0); ACCUM(u1); ACCUM(u2); ACCUM(u3);
        ACCUM(u4); ACCUM(u5); ACCUM(u6); ACCUM(u7);
        #undef ACCUM
    }

    // merge the two edge-subset halves (lanes l and l+16 hold same columns)
    a0 += __shfl_xor_sync(0xffffffffu, a0, 16);
    a1 += __shfl_xor_sync(0xffffffffu, a1, 16);
    a2 += __shfl_xor_sync(0xffffffffu, a2, 16);
    a3 += __shfl_xor_sync(0xffffffffu, a3, 16);

    float inv = 1.0f / fmaxf((float)cnt, 1.0f);
    float4 zz = *(const float4*)(g_z + (size_t)warp * D_OUT + (l << 2));
    float4 bb = *(const float4*)(b_l + (l << 2));
    float v0 = a0 * inv + bb.x + zz.x;
    float v1 = a1 * inv + bb.y + zz.y;
    float v2 = a2 * inv + bb.z + zz.z;
    float v3 = a3 * inv + bb.w + zz.w;

    // softmax over 64 cols: both 16-lane halves hold identical data, so a
    // full-warp butterfly over offsets 8..1 reduces correctly.
    float m = fmaxf(fmaxf(v0, v1), fmaxf(v2, v3));
    #pragma unroll
    for (int o = 8; o; o >>= 1) m = fmaxf(m, __shfl_xor_sync(0xffffffffu, m, o));

    float s = __expf(v0 - m) + __expf(v1 - m) + __expf(v2 - m) + __expf(v3 - m);
    #pragma unroll
    for (int o = 8; o; o >>= 1) s += __shfl_xor_sync(0xffffffffu, s, o);

    float lz = m + __logf(s);
    if (sub == 0)
        *(float4*)(out + (size_t)warp * D_OUT + (l << 2)) =
            make_float4(v0 - lz, v1 - lz, v2 - lz, v3 - lz);

    // reset the counter for the next graph replay (fill assumes zeros)
    if (lane == 0) g_cnt[warp] = 0;
}

// ---------------------------------------------------------------------------
extern "C" void kernel_launch(void* const* d_in, const int* in_sizes, int n_in,
                              void* d_out, int out_size) {
    const float* x  = (const float*)d_in[0];
    const float* Wl = (const float*)d_in[1];
    const float* bl = (const float*)d_in[2];
    const float* Wr = (const float*)d_in[3];
    const void*  ei = d_in[4];
    int n_edges = in_sizes[4] / 2;
    float* out = (float*)d_out;

    static bool attr_done = false;
    if (!attr_done) {
        attr_done = true;
        cudaFuncSetAttribute(prep_kernel,
                             cudaFuncAttributeMaxDynamicSharedMemorySize, SM_PREP);
        cudaFuncSetAttribute(gemm_mma_kernel,
                             cudaFuncAttributeMaxDynamicSharedMemorySize, SM_GEMM);
    }

    fill_kernel<<<2048, 256>>>(ei, n_edges);
    prep_kernel<<<2, 256, SM_PREP>>>(Wl, Wr);
    gemm_mma_kernel<<<TILES_Y + TILES_Z, 128, SM_GEMM>>>(x);
    gather_finalize_kernel<<<(N_DST * 32 + 255) / 256, 256>>>(out, bl);
}

// round 15
// speedup vs baseline: 1.2291x; 1.1239x over previous
#include <cuda_runtime.h>
#include <cuda_fp16.h>
#include <cuda_bf16.h>
#include <math.h>
#include <stdint.h>

#define N_SRC 100000
#define N_DST 50000
#define D_IN  128
#define D_OUT 64
#define BUCKET 128

#define TILES_Y 1563           // ceil(100000/64)
#define TILES_Z 782            // ceil(50000/64)
#define ASTR 136

// ---------------- scratch (device globals; no allocations allowed) ---------
__device__ __half g_yh[(size_t)N_SRC * D_OUT];     // fp16(x @ W_l)   12.8 MB
__device__ float  g_z[(size_t)N_DST * D_OUT];      // x[:N_DST]@W_r   12.8 MB
__device__ int    g_cnt[N_DST];                    // zero-init; gather re-zeroes
__device__ int    g_src[(size_t)N_DST * BUCKET];   // bucketed CSR    25.6 MB
// Pre-swizzled fp16 B fragments (exact ldmatrix register images), per type
__device__ uint4 g_bf[2][1024];                    // 32 KB

__device__ __forceinline__ uint32_t smem_u32(const void* p) {
    uint32_t a;
    asm("{ .reg .u64 t; cvta.to.shared.u64 t, %1; cvt.u32.u64 %0, t; }"
        : "=r"(a) : "l"(p));
    return a;
}

// ---------------------------------------------------------------------------
// prep: per-type (blockIdx.x: 0=W_l, 1=W_r) build fp16 W^T tile in smem, then
// warp 0 runs the gemm's exact b-ldmatrix pattern and stores the fragment
// registers to global. Never touches g_cnt/g_src.
__global__ __launch_bounds__(256) void prep_kernel(const float* __restrict__ Wl,
                                                   const float* __restrict__ Wr) {
    extern __shared__ __align__(16) char psm[];
    __half* B = (__half*)psm;                          // 64 x 136
    int type = blockIdx.x;
    const float* W = type ? Wr : Wl;
    int tid = threadIdx.x;

    for (int i = tid; i < 64 * 128; i += 256) {
        int n = i >> 7, k = i & 127;
        B[n * ASTR + k] = __float2half_rn(W[k * 64 + n]);  // W^T[n][k]
    }
    __syncthreads();

    if (tid < 32) {
        int lane = tid;
        uint32_t bb = smem_u32(B);
        uint32_t boff = (((((lane >> 4) << 3) + (lane & 7)) * ASTR +
                         (((lane >> 3) & 1) << 3)) << 1);
        #pragma unroll
        for (int k = 0; k < 8; k++) {
            #pragma unroll
            for (int p = 0; p < 4; p++) {
                uint32_t po = ((p * ASTR) << 5) + (k << 5);
                uint32_t u0, u1, u2, u3;
                asm volatile("ldmatrix.sync.aligned.m8n8.x4.shared.b16 {%0,%1,%2,%3}, [%4];"
                             : "=r"(u0), "=r"(u1), "=r"(u2), "=r"(u3)
                             : "r"(bb + boff + po));
                g_bf[type][((k << 2) + p) * 32 + lane] = make_uint4(u0, u1, u2, u3);
            }
        }
    }
}
#define SM_PREP (64 * ASTR * 2)

// ---------------------------------------------------------------------------
__global__ void fill_kernel(const void* __restrict__ eiv, int n_edges) {
    const unsigned long long* q = (const unsigned long long*)eiv;
    bool is64 = (((q[0] | q[1] | q[2] | q[3]) >> 32) == 0ULL);

    int stride = gridDim.x * blockDim.x;
    for (int e = blockIdx.x * blockDim.x + threadIdx.x; e < n_edges; e += stride) {
        int s, d;
        if (is64) {
            const long long* ei = (const long long*)eiv;
            s = (int)ei[e];
            d = (int)ei[n_edges + e];
        } else {
            const int* ei = (const int*)eiv;
            s = ei[e];
            d = ei[n_edges + e];
        }
        int slot = atomicAdd(&g_cnt[d], 1);
        if (slot < BUCKET)
            g_src[(size_t)d * BUCKET + slot] = s;
    }
}

// ---------------------------------------------------------------------------
// Single-pass fp16 HMMA GEMM: 64x64 tile per CTA, 4 warps, 6 CTAs/SM.
// C(fp32) = half(A) @ half(W); B fragments pre-swizzled in global (L1-hot).
__global__ __launch_bounds__(128, 6) void gemm_mma_kernel(const float* __restrict__ x) {
    extern __shared__ __align__(16) char smem_raw[];
    __half* A = (__half*)smem_raw;                       // 64 x 136 fp16

    int tid = threadIdx.x, warp = tid >> 5, lane = tid & 31;

    int b = blockIdx.x;
    bool is_y;
    int row0, M;
    if (b < TILES_Y) { row0 = b << 6;             M = N_SRC; is_y = true;  }
    else             { row0 = (b - TILES_Y) << 6; M = N_DST; is_y = false; }
    const uint4* bf = g_bf[is_y ? 0 : 1];

    // Load x tile (64x128 fp32) -> fp16 smem
    #pragma unroll
    for (int i = tid; i < 64 * 32; i += 128) {
        int row = i >> 5, c4 = (i & 31) << 2;
        float4 v = make_float4(0.f, 0.f, 0.f, 0.f);
        if (row0 + row < M)
            v = *(const float4*)(x + (size_t)(row0 + row) * D_IN + c4);
        __half2 h01 = __floats2half2_rn(v.x, v.y);
        __half2 h23 = __floats2half2_rn(v.z, v.w);
        *(uint2*)(A + row * ASTR + c4) =
            make_uint2(*(uint32_t*)&h01, *(uint32_t*)&h23);
    }
    __syncthreads();

    int m0 = warp << 4;
    float c[8][4];
    #pragma unroll
    for (int n = 0; n < 8; n++)
        #pragma unroll
        for (int j = 0; j < 4; j++) c[n][j] = 0.f;

    uint32_t ab = smem_u32(A);
    uint32_t aoff = (((m0 + (lane & 15)) * ASTR + ((lane >> 4) << 3)) << 1);

    #pragma unroll
    for (int k = 0; k < 8; k++) {
        uint32_t x0, x1, x2, x3;
        asm volatile("ldmatrix.sync.aligned.m8n8.x4.shared.b16 {%0,%1,%2,%3}, [%4];"
                     : "=r"(x0), "=r"(x1), "=r"(x2), "=r"(x3)
                     : "r"(ab + aoff + (k << 5)));
        #pragma unroll
        for (int p = 0; p < 4; p++) {
            uint4 U = bf[((k << 2) + p) * 32 + lane];
            int n = p << 1;
            asm volatile(
                "mma.sync.aligned.m16n8k16.row.col.f32.f16.f16.f32 "
                "{%0,%1,%2,%3}, {%4,%5,%6,%7}, {%8,%9}, {%0,%1,%2,%3};"
                : "+f"(c[n][0]), "+f"(c[n][1]), "+f"(c[n][2]), "+f"(c[n][3])
                : "r"(x0), "r"(x1), "r"(x2), "r"(x3), "r"(U.x), "r"(U.y));
            asm volatile(
                "mma.sync.aligned.m16n8k16.row.col.f32.f16.f16.f32 "
                "{%0,%1,%2,%3}, {%4,%5,%6,%7}, {%8,%9}, {%0,%1,%2,%3};"
                : "+f"(c[n+1][0]), "+f"(c[n+1][1]), "+f"(c[n+1][2]), "+f"(c[n+1][3])
                : "r"(x0), "r"(x1), "r"(x2), "r"(x3), "r"(U.z), "r"(U.w));
        }
    }

    // Epilogue: c fragment (row gr=lane/4 [+8], cols n*8 + 2*(lane%4) +{0,1})
    int gr = lane >> 2, gc = (lane & 3) << 1;
    int r0 = row0 + m0 + gr;
    int r1 = r0 + 8;
    if (is_y) {
        #pragma unroll
        for (int n = 0; n < 8; n++) {
            int col = (n << 3) + gc;
            if (r0 < M)
                *(__half2*)(g_yh + (size_t)r0 * D_OUT + col) =
                    __floats2half2_rn(c[n][0], c[n][1]);
            if (r1 < M)
                *(__half2*)(g_yh + (size_t)r1 * D_OUT + col) =
                    __floats2half2_rn(c[n][2], c[n][3]);
        }
    } else {
        #pragma unroll
        for (int n = 0; n < 8; n++) {
            int col = (n << 3) + gc;
            if (r0 < M)
                *(float2*)(g_z + (size_t)r0 * D_OUT + col) = make_float2(c[n][0], c[n][1]);
            if (r1 < M)
                *(float2*)(g_z + (size_t)r1 * D_OUT + col) = make_float2(c[n][2], c[n][3]);
        }
    }
}
#define SM_GEMM (64 * ASTR * 2)

// ---------------------------------------------------------------------------
// Gather + finalize (R14, measured 33.4us): one warp per dst row, 16 lanes
// per row (uint2 = 8B = cols 4l..4l+3), sub-half-warps take alternate edges.
// 8 predicated independent LDG.64 in flight per lane => 16 edges/iter, MLP=8.
// Re-zeroes g_cnt[warp] at the end.
__global__ __launch_bounds__(256) void gather_finalize_kernel(
        float* __restrict__ out, const float* __restrict__ b_l) {
    int warp = (blockIdx.x * blockDim.x + threadIdx.x) >> 5;
    int lane = threadIdx.x & 31;
    if (warp >= N_DST) return;

    int cnt = g_cnt[warp];
    int n = cnt < BUCKET ? cnt : BUCKET;
    const int* bucket = g_src + (size_t)warp * BUCKET;
    int sub = lane >> 4, l = lane & 15;
    const uint2* yh2 = (const uint2*)g_yh + l;     // row r -> yh2[r*16]

    float a0 = 0.f, a1 = 0.f, a2 = 0.f, a3 = 0.f;
    uint2 zero2 = make_uint2(0u, 0u);
    for (int g = 0; g < n; g += 16) {
        int4 c0 = *(const int4*)(bucket + g);
        int4 c1 = *(const int4*)(bucket + g + 4);
        int4 c2 = *(const int4*)(bucket + g + 8);
        int4 c3 = *(const int4*)(bucket + g + 12);
        int s0 = sub ? c0.y : c0.x;
        int s1 = sub ? c0.w : c0.z;
        int s2 = sub ? c1.y : c1.x;
        int s3 = sub ? c1.w : c1.z;
        int s4 = sub ? c2.y : c2.x;
        int s5 = sub ? c2.w : c2.z;
        int s6 = sub ? c3.y : c3.x;
        int s7 = sub ? c3.w : c3.z;
        uint2 u0 = (g + 0  + sub < n) ? yh2[(size_t)s0 << 4] : zero2;
        uint2 u1 = (g + 2  + sub < n) ? yh2[(size_t)s1 << 4] : zero2;
        uint2 u2 = (g + 4  + sub < n) ? yh2[(size_t)s2 << 4] : zero2;
        uint2 u3 = (g + 6  + sub < n) ? yh2[(size_t)s3 << 4] : zero2;
        uint2 u4 = (g + 8  + sub < n) ? yh2[(size_t)s4 << 4] : zero2;
        uint2 u5 = (g + 10 + sub < n) ? yh2[(size_t)s5 << 4] : zero2;
        uint2 u6 = (g + 12 + sub < n) ? yh2[(size_t)s6 << 4] : zero2;
        uint2 u7 = (g + 14 + sub < n) ? yh2[(size_t)s7 << 4] : zero2;
        #define ACCUM(U)                                                        \
            { float2 fl = __half22float2(*(__half2*)&(U).x);                    \
              float2 fh = __half22float2(*(__half2*)&(U).y);                    \
              a0 += fl.x; a1 += fl.y; a2 += fh.x; a3 += fh.y; }
        ACCUM(u0); ACCUM(u1); ACCUM(u2); ACCUM(u3);
        ACCUM(u4); ACCUM(u5); ACCUM(u6); ACCUM(u7);
        #undef ACCUM
    }

    a0 += __shfl_xor_sync(0xffffffffu, a0, 16);
    a1 += __shfl_xor_sync(0xffffffffu, a1, 16);
    a2 += __shfl_xor_sync(0xffffffffu, a2, 16);
    a3 += __shfl_xor_sync(0xffffffffu, a3, 16);

    float inv = 1.0f / fmaxf((float)cnt, 1.0f);
    float4 zz = *(const float4*)(g_z + (size_t)warp * D_OUT + (l << 2));
    float4 bb = *(const float4*)(b_l + (l << 2));
    float v0 = a0 * inv + bb.x + zz.x;
    float v1 = a1 * inv + bb.y + zz.y;
    float v2 = a2 * inv + bb.z + zz.z;
    float v3 = a3 * inv + bb.w + zz.w;

    float m = fmaxf(fmaxf(v0, v1), fmaxf(v2, v3));
    #pragma unroll
    for (int o = 8; o; o >>= 1) m = fmaxf(m, __shfl_xor_sync(0xffffffffu, m, o));

    float s = __expf(v0 - m) + __expf(v1 - m) + __expf(v2 - m) + __expf(v3 - m);
    #pragma unroll
    for (int o = 8; o; o >>= 1) s += __shfl_xor_sync(0xffffffffu, s, o);

    float lz = m + __logf(s);
    if (sub == 0)
        *(float4*)(out + (size_t)warp * D_OUT + (l << 2)) =
            make_float4(v0 - lz, v1 - lz, v2 - lz, v3 - lz);

    if (lane == 0) g_cnt[warp] = 0;
}

// ---------------------------------------------------------------------------
extern "C" void kernel_launch(void* const* d_in, const int* in_sizes, int n_in,
                              void* d_out, int out_size) {
    const float* x  = (const float*)d_in[0];
    const float* Wl = (const float*)d_in[1];
    const float* bl = (const float*)d_in[2];
    const float* Wr = (const float*)d_in[3];
    const void*  ei = d_in[4];
    int n_edges = in_sizes[4] / 2;
    float* out = (float*)d_out;

    static bool attr_done = false;
    if (!attr_done) {
        attr_done = true;
        cudaFuncSetAttribute(prep_kernel,
                             cudaFuncAttributeMaxDynamicSharedMemorySize, SM_PREP);
        cudaFuncSetAttribute(gemm_mma_kernel,
                             cudaFuncAttributeMaxDynamicSharedMemorySize, SM_GEMM);
    }

    fill_kernel<<<2048, 256>>>(ei, n_edges);
    prep_kernel<<<2, 256, SM_PREP>>>(Wl, Wr);
    gemm_mma_kernel<<<TILES_Y + TILES_Z, 128, SM_GEMM>>>(x);
    gather_finalize_kernel<<<(N_DST * 32 + 255) / 256, 256>>>(out, bl);
}